// round 5
// baseline (speedup 1.0000x reference)
#include <cuda_runtime.h>
#include <math.h>

// Shapes (fixed by the problem)
// B=8 T=512 D=512 H=8 DK=DV=128 M=2 S=2 (MS=4) L=512 G=4
// inputs (metadata order):
//  0 trg_rep   [8,512,512] f32
//  1 guider_rep[8,4,512]   f32
//  2 low_reps  [2,2,8,512,512] f32
//  3 Wq        [512,1024]
//  4 Wk_guider [2,512,1024]
//  5 Wk_low    [2,512,1024]
//  6 Wv_low    [2,512,1024]
//  7 Wfc       [1024,512]
//  8 gamma[512]  9 beta[512]
// 10 guider_mask [8,512,4] i32
// 11 low_mask    [2,2,8,512,512] i32
// output: out [8,512,512] (2,097,152) ++ final_att [8,8,512,2048] (67,108,864)

// ---------------- scratch (static device globals; no runtime alloc) ----------
__device__ float g_x   [(size_t)4096*512];        //  8 MB  LN(trg)
__device__ float g_qs  [(size_t)64*512*128];      // 16 MB  [b,h,t,dk], pre-scaled 1/sqrt(128)
__device__ float g_gk  [64*4*128];                //        [b,h,g,dk]
__device__ float g_gatt[64*512*4];                //        [b,h,t,g]
__device__ float g_lk  [(size_t)32*512*1024];     // 64 MB  [ms*8+b, l, h*128+dk]
__device__ float g_lv  [(size_t)32*512*1024];     // 64 MB  same layout
__device__ float g_o1  [(size_t)4096*1024];       // 16 MB  [b,t,h,dv]
__device__ float g_att_fallback[(size_t)67108864];// insurance if out_size lacks final_att

// ---------------- LayerNorm: one block per row (4096 rows, 128 thr) ----------
__global__ void ln_kernel(const float* __restrict__ x,
                          const float* __restrict__ gamma,
                          const float* __restrict__ beta) {
    const int row = blockIdx.x;
    const int tid = threadIdx.x;                 // 128
    float4 v = reinterpret_cast<const float4*>(x + (size_t)row * 512)[tid];

    __shared__ float sh[4], sh2[4];
    float s = v.x + v.y + v.z + v.w;
    #pragma unroll
    for (int o = 16; o; o >>= 1) s += __shfl_xor_sync(0xffffffffu, s, o);
    if ((tid & 31) == 0) sh[tid >> 5] = s;
    __syncthreads();
    const float mu = (sh[0] + sh[1] + sh[2] + sh[3]) * (1.f / 512.f);

    const float d0 = v.x - mu, d1 = v.y - mu, d2 = v.z - mu, d3 = v.w - mu;
    float s2 = d0 * d0 + d1 * d1 + d2 * d2 + d3 * d3;
    #pragma unroll
    for (int o = 16; o; o >>= 1) s2 += __shfl_xor_sync(0xffffffffu, s2, o);
    if ((tid & 31) == 0) sh2[tid >> 5] = s2;
    __syncthreads();
    const float var = (sh2[0] + sh2[1] + sh2[2] + sh2[3]) * (1.f / 512.f);
    const float rstd = rsqrtf(var + 1e-6f);

    float4 g  = reinterpret_cast<const float4*>(gamma)[tid];
    float4 bt = reinterpret_cast<const float4*>(beta)[tid];
    float4 o;
    o.x = d0 * rstd * g.x + bt.x;
    o.y = d1 * rstd * g.y + bt.y;
    o.z = d2 * rstd * g.z + bt.z;
    o.w = d3 * rstd * g.w + bt.w;
    reinterpret_cast<float4*>(g_x + (size_t)row * 512)[tid] = o;
}

// ---------------- guider keys: gk[b,h,g,k] (32 blocks × 256 thr) -------------
__global__ void gk_kernel(const float* __restrict__ guid,
                          const float* __restrict__ Wkg) {
    const int b = blockIdx.x >> 2;
    const int g = blockIdx.x & 3;
    const int m = g >> 1;                        // S = 2
    __shared__ float sg[512];
    const int tid = threadIdx.x;                 // 256
    sg[tid]       = guid[(size_t)(b * 4 + g) * 512 + tid];
    sg[tid + 256] = guid[(size_t)(b * 4 + g) * 512 + tid + 256];
    __syncthreads();

    const int e0 = tid * 4;                      // 1024 outputs / 256 thr
    float4 acc = make_float4(0.f, 0.f, 0.f, 0.f);
    const float* W = Wkg + (size_t)m * 512 * 1024 + e0;
    #pragma unroll 4
    for (int d = 0; d < 512; ++d) {
        const float gv = sg[d];
        float4 w = *reinterpret_cast<const float4*>(W + (size_t)d * 1024);
        acc.x = fmaf(gv, w.x, acc.x);
        acc.y = fmaf(gv, w.y, acc.y);
        acc.z = fmaf(gv, w.z, acc.z);
        acc.w = fmaf(gv, w.w, acc.w);
    }
    const int h = e0 >> 7, k = e0 & 127;
    *reinterpret_cast<float4*>(&g_gk[((size_t)(b * 8 + h) * 4 + g) * 128 + k]) = acc;
}

// ---------------- guider attention: g_att[b,h,t,g] (32768 blocks × 128) ------
__global__ void gatt_kernel(const int* __restrict__ gmask) {
    const int idx  = blockIdx.x;                 // (b*8+h)*512 + t
    const int t    = idx & 511;
    const int b    = idx >> 12;
    const int lane = threadIdx.x & 31;
    const int g    = threadIdx.x >> 5;           // 4 warps, one per g

    const float* qrow = g_qs + (size_t)idx * 128;
    const float* krow = g_gk + ((size_t)(idx >> 9) * 4 + g) * 128; // (b*8+h)*4+g
    float4 q4 = reinterpret_cast<const float4*>(qrow)[lane];
    float4 k4 = reinterpret_cast<const float4*>(krow)[lane];
    float p = q4.x * k4.x + q4.y * k4.y + q4.z * k4.z + q4.w * k4.w;
    #pragma unroll
    for (int o = 16; o; o >>= 1) p += __shfl_xor_sync(0xffffffffu, p, o);

    __shared__ float sc[4];
    if (lane == 0)
        sc[g] = (gmask[(size_t)(b * 512 + t) * 4 + g] != 0) ? p : -1e9f;
    __syncthreads();
    if (threadIdx.x < 4) {
        const float mx = fmaxf(fmaxf(sc[0], sc[1]), fmaxf(sc[2], sc[3]));
        const float e0 = expf(sc[0] - mx), e1 = expf(sc[1] - mx);
        const float e2 = expf(sc[2] - mx), e3 = expf(sc[3] - mx);
        const float e[4] = {e0, e1, e2, e3};
        g_gatt[(size_t)idx * 4 + threadIdx.x] = e[threadIdx.x] / (e0 + e1 + e2 + e3);
    }
}

// ---------------- masked softmax over L, ×g_att, in-place on final_att -------
// block = (b,t,ms); 8 warps = 8 heads; mask row shared across warps
__global__ void lsoftmax_kernel(float* __restrict__ att,
                                const int* __restrict__ lmask) {
    const int idx  = blockIdx.x;                 // (b*512+t)*4 + ms
    const int ms   = idx & 3;
    const int t    = (idx >> 2) & 511;
    const int b    = idx >> 11;
    const int h    = threadIdx.x >> 5;
    const int lane = threadIdx.x & 31;

    float* row = att + ((size_t)(b * 8 + h) * 512 + t) * 2048 + ms * 512;
    const int* mrow = lmask + ((size_t)(ms * 8 + b) * 512 + t) * 512;

    float4 v[4];
    float mx = -3.0e38f;
    #pragma unroll
    for (int q = 0; q < 4; ++q) {
        v[q] = reinterpret_cast<const float4*>(row)[q * 32 + lane];
        int4 mk = reinterpret_cast<const int4*>(mrow)[q * 32 + lane];
        if (!mk.x) v[q].x = -1e9f;
        if (!mk.y) v[q].y = -1e9f;
        if (!mk.z) v[q].z = -1e9f;
        if (!mk.w) v[q].w = -1e9f;
        mx = fmaxf(mx, fmaxf(fmaxf(v[q].x, v[q].y), fmaxf(v[q].z, v[q].w)));
    }
    #pragma unroll
    for (int o = 16; o; o >>= 1) mx = fmaxf(mx, __shfl_xor_sync(0xffffffffu, mx, o));

    float sum = 0.f;
    #pragma unroll
    for (int q = 0; q < 4; ++q) {
        v[q].x = __expf(v[q].x - mx);
        v[q].y = __expf(v[q].y - mx);
        v[q].z = __expf(v[q].z - mx);
        v[q].w = __expf(v[q].w - mx);
        sum += v[q].x + v[q].y + v[q].z + v[q].w;
    }
    #pragma unroll
    for (int o = 16; o; o >>= 1) sum += __shfl_xor_sync(0xffffffffu, sum, o);

    const float scl = g_gatt[((size_t)(b * 8 + h) * 512 + t) * 4 + ms] / sum;
    #pragma unroll
    for (int q = 0; q < 4; ++q) {
        v[q].x *= scl; v[q].y *= scl; v[q].z *= scl; v[q].w *= scl;
        reinterpret_cast<float4*>(row)[q * 32 + lane] = v[q];
    }
}

// ---------------- SGEMM 128x128x16, 256 thr, 8x8 microtile -------------------
// MODE 0: g_qs = g_x @ Wq            (scale 1/sqrt(128), scatter [b,h,t,dk])
// MODE 1: g_lk/g_lv = low_reps @ Wk/Wv_low   (z = slab 0..31)
// MODE 2: scores = qs @ lk^T  -> Y (final_att region), z = ms*64+b*8+h
// MODE 3: g_o1 = final_att @ cat_v (gathered B from g_lv), z = b*8+h
// MODE 4: d_out = g_o1 @ Wfc + residual
template <int MODE>
__global__ void __launch_bounds__(256, 2)
gemm_kernel(const float* __restrict__ X0, const float* __restrict__ X1,
            const float* __restrict__ X2, float* __restrict__ Y) {
    constexpr int BK = 16;
    __shared__ __align__(16) float As[BK][128];
    __shared__ __align__(16) float Bs[BK][128];

    const int tid = threadIdx.x;
    const int tx = tid & 15;
    const int ty = tid >> 4;
    const int bn = blockIdx.x;
    const int bm = blockIdx.y;
    const int bz = blockIdx.z;

    const float* Ap = nullptr;
    const float* Bp = nullptr;
    const float* Kp = nullptr;
    int lda = 0, ldb = 0, Kdim = 0;
    int msF = 0, bF = 0, hF = 0;

    if (MODE == 0) {
        Ap = g_x + (size_t)bm * 128 * 512; lda = 512; Kdim = 512;
        Bp = X0 + bn * 128; ldb = 1024;                // Wq
    } else if (MODE == 1) {
        Ap = X0 + (size_t)bz * 512 * 512 + (size_t)bm * 128 * 512; // low_reps slab
        lda = 512; Kdim = 512;
        const int m = bz >> 4;
        const int c0 = bn * 128;
        Bp = (c0 < 1024) ? (X1 + (size_t)m * 512 * 1024 + c0)
                         : (X2 + (size_t)m * 512 * 1024 + (c0 - 1024));
        ldb = 1024;
    } else if (MODE == 2) {
        msF = bz >> 6; bF = (bz >> 3) & 7; hF = bz & 7;
        Ap = g_qs + ((size_t)(bF * 8 + hF) * 512 + bm * 128) * 128;
        lda = 128; Kdim = 128;
        Kp = g_lk + (size_t)(msF * 8 + bF) * 512 * 1024
                  + (size_t)(bn * 128) * 1024 + hF * 128;
    } else if (MODE == 3) {
        bF = bz >> 3; hF = bz & 7;
        Ap = X0 + (size_t)bz * 512 * 2048 + (size_t)bm * 128 * 2048; // final_att
        lda = 2048; Kdim = 2048;
    } else {
        Ap = g_o1 + (size_t)bm * 128 * 1024; lda = 1024; Kdim = 1024;
        Bp = X0 + bn * 128; ldb = 512;                 // Wfc
    }

    const int ar = tid >> 2;
    const int ac = (tid & 3) << 2;
    const int br = tid >> 5;
    const int bc = (tid & 31) << 2;

    float acc[8][8];
    #pragma unroll
    for (int i = 0; i < 8; ++i)
        #pragma unroll
        for (int j = 0; j < 8; ++j) acc[i][j] = 0.f;

    for (int kt = 0; kt < Kdim; kt += BK) {
        #pragma unroll
        for (int p = 0; p < 2; ++p) {                  // A tile (transposed store)
            const int m = ar + p * 64;
            float4 v = *reinterpret_cast<const float4*>(Ap + (size_t)m * lda + kt + ac);
            As[ac + 0][m] = v.x; As[ac + 1][m] = v.y;
            As[ac + 2][m] = v.z; As[ac + 3][m] = v.w;
        }
        if (MODE == 2) {                               // B = K^T (lk rows, stride 1024)
            #pragma unroll
            for (int p = 0; p < 2; ++p) {
                const int n = ar + p * 64;
                float4 v = *reinterpret_cast<const float4*>(Kp + (size_t)n * 1024 + kt + ac);
                Bs[ac + 0][n] = v.x; Bs[ac + 1][n] = v.y;
                Bs[ac + 2][n] = v.z; Bs[ac + 3][n] = v.w;
            }
        } else if (MODE == 3) {                        // gathered cat_v rows from g_lv
            const int msk = kt >> 9, lb = kt & 511;
            const float* Bc2 = g_lv + ((size_t)(msk * 8 + bF) * 512 + lb) * 1024 + hF * 128;
            #pragma unroll
            for (int p = 0; p < 2; ++p) {
                const int k = br + p * 8;
                float4 v = *reinterpret_cast<const float4*>(Bc2 + (size_t)k * 1024 + bc);
                *reinterpret_cast<float4*>(&Bs[k][bc]) = v;
            }
        } else {
            #pragma unroll
            for (int p = 0; p < 2; ++p) {
                const int k = br + p * 8;
                float4 v = *reinterpret_cast<const float4*>(Bp + (size_t)(kt + k) * ldb + bc);
                *reinterpret_cast<float4*>(&Bs[k][bc]) = v;
            }
        }
        __syncthreads();
        #pragma unroll
        for (int k = 0; k < BK; ++k) {
            float4 a0 = *reinterpret_cast<const float4*>(&As[k][ty * 8]);
            float4 a1 = *reinterpret_cast<const float4*>(&As[k][ty * 8 + 4]);
            float4 b0 = *reinterpret_cast<const float4*>(&Bs[k][tx * 8]);
            float4 b1 = *reinterpret_cast<const float4*>(&Bs[k][tx * 8 + 4]);
            const float av[8] = {a0.x, a0.y, a0.z, a0.w, a1.x, a1.y, a1.z, a1.w};
            const float bv[8] = {b0.x, b0.y, b0.z, b0.w, b1.x, b1.y, b1.z, b1.w};
            #pragma unroll
            for (int i = 0; i < 8; ++i)
                #pragma unroll
                for (int j = 0; j < 8; ++j)
                    acc[i][j] = fmaf(av[i], bv[j], acc[i][j]);
        }
        __syncthreads();
    }

    // ---- epilogue ----
    #pragma unroll
    for (int i = 0; i < 8; ++i) {
        float4 o0 = make_float4(acc[i][0], acc[i][1], acc[i][2], acc[i][3]);
        float4 o1 = make_float4(acc[i][4], acc[i][5], acc[i][6], acc[i][7]);
        if (MODE == 0) {
            const float sc = 0.08838834764831845f;     // 1/sqrt(128)
            o0.x *= sc; o0.y *= sc; o0.z *= sc; o0.w *= sc;
            o1.x *= sc; o1.y *= sc; o1.z *= sc; o1.w *= sc;
            const int r = bm * 128 + ty * 8 + i;
            const int b = r >> 9, t = r & 511;
            float* dst = g_qs + ((size_t)((b * 8 + bn) * 512 + t)) * 128 + tx * 8;
            *reinterpret_cast<float4*>(dst) = o0;
            *reinterpret_cast<float4*>(dst + 4) = o1;
        } else if (MODE == 1) {
            const int r = bm * 128 + ty * 8 + i;
            const int c0 = bn * 128;
            float* base = (c0 < 1024) ? (g_lk + (size_t)bz * 512 * 1024 + c0)
                                      : (g_lv + (size_t)bz * 512 * 1024 + (c0 - 1024));
            float* dst = base + (size_t)r * 1024 + tx * 8;
            *reinterpret_cast<float4*>(dst) = o0;
            *reinterpret_cast<float4*>(dst + 4) = o1;
        } else if (MODE == 2) {
            const int t = bm * 128 + ty * 8 + i;
            float* dst = Y + ((size_t)(bF * 8 + hF) * 512 + t) * 2048
                           + msF * 512 + bn * 128 + tx * 8;
            *reinterpret_cast<float4*>(dst) = o0;
            *reinterpret_cast<float4*>(dst + 4) = o1;
        } else if (MODE == 3) {
            const int t = bm * 128 + ty * 8 + i;
            float* dst = g_o1 + ((size_t)bF * 512 + t) * 1024 + hF * 128 + tx * 8;
            *reinterpret_cast<float4*>(dst) = o0;
            *reinterpret_cast<float4*>(dst + 4) = o1;
        } else {
            const int r = bm * 128 + ty * 8 + i;
            const int c = bn * 128 + tx * 8;
            float4 r0 = *reinterpret_cast<const float4*>(X1 + (size_t)r * 512 + c);
            float4 r1 = *reinterpret_cast<const float4*>(X1 + (size_t)r * 512 + c + 4);
            o0.x += r0.x; o0.y += r0.y; o0.z += r0.z; o0.w += r0.w;
            o1.x += r1.x; o1.y += r1.y; o1.z += r1.z; o1.w += r1.w;
            float* dst = Y + (size_t)r * 512 + c;
            *reinterpret_cast<float4*>(dst) = o0;
            *reinterpret_cast<float4*>(dst + 4) = o1;
        }
    }
}

// ---------------- launch ------------------------------------------------------
extern "C" void kernel_launch(void* const* d_in, const int* in_sizes, int n_in,
                              void* d_out, int out_size) {
    const float* trg   = (const float*)d_in[0];
    const float* guid  = (const float*)d_in[1];
    const float* lowr  = (const float*)d_in[2];
    const float* Wq    = (const float*)d_in[3];
    const float* Wkg   = (const float*)d_in[4];
    const float* Wkl   = (const float*)d_in[5];
    const float* Wvl   = (const float*)d_in[6];
    const float* Wfc   = (const float*)d_in[7];
    const float* gamma = (const float*)d_in[8];
    const float* beta  = (const float*)d_in[9];
    const int*   gmask = (const int*)d_in[10];
    const int*   lmask = (const int*)d_in[11];

    float* out = (float*)d_out;
    // final_att follows `out` in the flattened tuple output; fall back to
    // scratch if the harness only sized d_out for `out`.
    float* att;
    if (out_size > 2097152) {
        att = out + (size_t)2097152;
    } else {
        cudaGetSymbolAddress((void**)&att, g_att_fallback);
    }

    // 1. LayerNorm
    ln_kernel<<<4096, 128>>>(trg, gamma, beta);
    // 2. qs = LN(x) @ Wq  (scaled, scattered to [b,h,t,dk])
    gemm_kernel<0><<<dim3(8, 32, 1), 256>>>(Wq, nullptr, nullptr, nullptr);
    // 3. guider keys + guider attention
    gk_kernel<<<32, 256>>>(guid, Wkg);
    gatt_kernel<<<32768, 128>>>(gmask);
    // 4. lk / lv projections (32 slabs, fused K|V over 2048 cols)
    gemm_kernel<1><<<dim3(16, 4, 32), 256>>>(lowr, Wkl, Wvl, nullptr);
    // 5. raw scores straight into the final_att output region
    gemm_kernel<2><<<dim3(4, 4, 256), 256>>>(nullptr, nullptr, nullptr, att);
    // 6. masked softmax over L, multiplied by g_att, in place
    lsoftmax_kernel<<<16384, 256>>>(att, lmask);
    // 7. o1 = final_att @ cat_v   ([b,t,h,dv])
    gemm_kernel<3><<<dim3(1, 4, 64), 256>>>(att, nullptr, nullptr, nullptr);
    // 8. out = o1 @ Wfc + residual
    gemm_kernel<4><<<dim3(4, 32, 1), 256>>>(Wfc, trg, nullptr, out);
}